// round 7
// baseline (speedup 1.0000x reference)
#include <cuda_runtime.h>
#include <cuda_fp16.h>
#include <cstdint>

#define CC 256
#define WW 128
#define HH 64
#define BB 2
#define NCOL (BB*HH)
#define HO 256
#define WO 512
#define NOUT (BB*HO*WO)
#define NROWS 512             // output rows (b,i)
#define NG 8                  // columns per CTA
#define ROWH 24               // B row stride in halfs (48 bytes: 32 data + 16 pad)

__device__ __half g_M[CC*CC];           // center-tap weights fp16, row-major [o][c]
__device__ float  g_u[NCOL*WW];
__device__ float  g_psum[NROWS];
__device__ float  g_psumsq[NROWS];
__device__ float  g_stats[2];

__device__ __forceinline__ uint32_t smem_u32(const void* p) {
    uint32_t a;
    asm("{ .reg .u64 t; cvta.to.shared.u64 t, %1; cvt.u32.u64 %0, t; }"
        : "=r"(a) : "l"(p));
    return a;
}

// ===========================================================================
__global__ void extract_M_kernel(const float* __restrict__ convw) {
    int i = blockIdx.x * 256 + threadIdx.x;
    g_M[i] = __float2half(convw[i * 9 + 4]);
}

// ===========================================================================
// HMMA double scan: 16 CTAs x 8 columns, 256 threads.
// Per step: D[256x16] = M[256x256] @ S[256x16], mma.sync m16n8k16.
// A = M resident in registers (128 regs/thread, loaded once).
// B = S fp16 double-buffered smem, k-major rows of 16 halfs padded to 48B.
// One ldmatrix.x4.trans per k16 chunk covers both n-halves:
//   lanes 0-15 -> k-rows (lane&15) at n 0..7, lanes 16-31 -> same k at n 8..15.
// Chunk stride = 16 rows * 48B = 768B.   <-- R6 bug was 384 here.
#define MMA_ASM(dd, a, b0r, b1r)                                              \
    asm volatile(                                                             \
        "mma.sync.aligned.m16n8k16.row.col.f32.f16.f16.f32 "                  \
        "{%0,%1,%2,%3}, {%4,%5,%6,%7}, {%8,%9}, {%0,%1,%2,%3};"               \
        : "+f"((dd)[0]), "+f"((dd)[1]), "+f"((dd)[2]), "+f"((dd)[3])          \
        : "r"((a)[0]), "r"((a)[1]), "r"((a)[2]), "r"((a)[3]),                 \
          "r"(b0r), "r"(b1r))

#define LDSM_T(L, addr)                                                       \
    asm volatile(                                                             \
        "ldmatrix.sync.aligned.m8n8.x4.trans.shared.b16 {%0,%1,%2,%3}, [%4];" \
        : "=r"((L)[0]), "=r"((L)[1]), "=r"((L)[2]), "=r"((L)[3])              \
        : "r"(addr))

__global__ void __launch_bounds__(256, 1) scnn_hmma_kernel(
        const float* __restrict__ p2, const float* __restrict__ w1g) {
    __shared__ __align__(128) __half Bbuf[2][CC * ROWH];   // 2 x 12KB
    __shared__ float wsum[2][8][8];

    const int tid  = threadIdx.x;
    const int wid  = tid >> 5;
    const int lane = tid & 31;
    const int tg   = lane & 3;
    const int g    = lane >> 2;
    const int col0 = blockIdx.x * NG;

    // ---- A fragments: M rows [32*wid, 32*wid+32)
    uint32_t A[2][16][4];
#pragma unroll
    for (int tt = 0; tt < 2; tt++) {
        int rlo = 32 * wid + 16 * tt + g;
        const uint32_t* Mlo = reinterpret_cast<const uint32_t*>(g_M + rlo * CC);
        const uint32_t* Mhi = reinterpret_cast<const uint32_t*>(g_M + (rlo + 8) * CC);
#pragma unroll
        for (int kt = 0; kt < 16; kt++) {
            A[tt][kt][0] = Mlo[kt * 8 + tg];
            A[tt][kt][1] = Mhi[kt * 8 + tg];
            A[tt][kt][2] = Mlo[kt * 8 + tg + 4];
            A[tt][kt][3] = Mhi[kt * 8 + tg + 4];
        }
    }

    // this thread's 4 channel rows, w1 taps, x offsets for its 2 columns
    int   chrow[4];          // ch * ROWH (half index of B row)
    float w1v[4];
    int   off[4][2];         // element offset into p2 for (ch, col) stream
#pragma unroll
    for (int i = 0; i < 4; i++) {
        int tt = i >> 1, hh = i & 1;
        int ch = 32 * wid + 16 * tt + 8 * hh + g;
        chrow[i] = ch * ROWH;
        w1v[i]   = w1g[ch];
#pragma unroll
        for (int nh = 0; nh < 2; nh++) {
            int col = col0 + tg + 4 * nh;
            int b = col >> 6, h = col & 63;
            off[i][nh] = ((b * CC + ch) * HH + h) * WW;
        }
    }

    const uint32_t b32 = smem_u32(&Bbuf[0][0]);
    // ldmatrix lane address within a buffer: k-row (lane&15), n-half (lane>>4)
    const uint32_t lmbase = b32 + (uint32_t)(lane & 15) * 48u
                                + (uint32_t)(lane >> 4) * 16u;

    // ---- step 0: s1[0] = s2[0] = x[:,0]  (write buffer 0)
    float xv[4][2];
    {
        float u0 = 0.f, u1 = 0.f;
#pragma unroll
        for (int i = 0; i < 4; i++) {
#pragma unroll
            for (int nh = 0; nh < 2; nh++) {
                float x0 = p2[off[i][nh]];
                __half hx = __float2half_rn(x0);
                *(__half2*)&Bbuf[0][chrow[i] + 2 * (tg + 4 * nh)] =
                    __halves2half2(hx, hx);
                if (nh) u1 += w1v[i] * x0; else u0 += w1v[i] * x0;
                xv[i][nh] = p2[off[i][nh] + 1];
            }
        }
#pragma unroll
        for (int o = 4; o <= 16; o <<= 1) {
            u0 += __shfl_xor_sync(0xffffffffu, u0, o);
            u1 += __shfl_xor_sync(0xffffffffu, u1, o);
        }
        if (lane < 4) { wsum[0][wid][lane] = u0; wsum[0][wid][lane + 4] = u1; }
    }

    for (int w = 1; w < WW; w++) {
        __syncthreads();
        if (tid < 8) {
            float s = 0.f;
#pragma unroll
            for (int q = 0; q < 8; q++) s += wsum[(w - 1) & 1][q][tid];
            g_u[(col0 + tid) * WW + (WW - w)] = s;
        }

        const int rb = (w - 1) & 1;
        const int wb = rb ^ 1;
        const uint32_t base = lmbase + (uint32_t)rb * (CC * ROWH * 2);

        float d[2][2][4] = {};
        float e[2][2][4] = {};
        uint32_t L[2][4];
        LDSM_T(L[0], base);

        // prefetch next x while MMAs run
        float xn[4][2];
        if (w < WW - 1) {
#pragma unroll
            for (int i = 0; i < 4; i++) {
                xn[i][0] = p2[off[i][0] + w + 1];
                xn[i][1] = p2[off[i][1] + w + 1];
            }
        }

#pragma unroll
        for (int kt = 0; kt < 16; kt++) {
            if (kt < 15) LDSM_T(L[(kt + 1) & 1], base + (uint32_t)(kt + 1) * 768u);
            const uint32_t* Lc = L[kt & 1];
            if (kt & 1) {
#pragma unroll
                for (int tt = 0; tt < 2; tt++) {
                    MMA_ASM(e[tt][0], A[tt][kt], Lc[0], Lc[1]);
                    MMA_ASM(e[tt][1], A[tt][kt], Lc[2], Lc[3]);
                }
            } else {
#pragma unroll
                for (int tt = 0; tt < 2; tt++) {
                    MMA_ASM(d[tt][0], A[tt][kt], Lc[0], Lc[1]);
                    MMA_ASM(d[tt][1], A[tt][kt], Lc[2], Lc[3]);
                }
            }
        }

        float u0 = 0.f, u1 = 0.f;
#pragma unroll
        for (int i = 0; i < 4; i++) {
            const int tt = i >> 1, hh = i & 1;
#pragma unroll
            for (int nh = 0; nh < 2; nh++) {
                float r1  = fmaxf(d[tt][nh][2*hh]   + e[tt][nh][2*hh],   0.f);
                float r2  = fmaxf(d[tt][nh][2*hh+1] + e[tt][nh][2*hh+1], 0.f);
                float s1n = xv[i][nh] + r1;
                float s2n = s1n + r2;
                if (nh) u1 += w1v[i] * s2n; else u0 += w1v[i] * s2n;
                if (w < WW - 1) {
                    *(__half2*)&Bbuf[wb][chrow[i] + 2 * (tg + 4 * nh)] =
                        __floats2half2_rn(s1n, s2n);
                    xv[i][nh] = xn[i][nh];
                }
            }
        }
#pragma unroll
        for (int o = 4; o <= 16; o <<= 1) {
            u0 += __shfl_xor_sync(0xffffffffu, u0, o);
            u1 += __shfl_xor_sync(0xffffffffu, u1, o);
        }
        if (lane < 4) {
            wsum[w & 1][wid][lane]     = u0;
            wsum[w & 1][wid][lane + 4] = u1;
        }
    }

    __syncthreads();
    if (tid < 8) {
        float s = 0.f;
#pragma unroll
        for (int q = 0; q < 8; q++) s += wsum[1][q][tid];   // w=127 -> buf 1
        g_u[(col0 + tid) * WW + 0] = s;
    }
}

// ===========================================================================
__device__ __forceinline__ void stage_rows(float* su0, float* su1,
                                           int b, int i, float& wy) {
    float ys = (float)i * (63.0f / 255.0f);
    int y0 = (int)ys;
    wy = ys - (float)y0;
    int y1 = min(y0 + 1, HH - 1);
    int t = threadIdx.x;
    if (t < 128)      su0[t]       = g_u[(b * HH + y0) * WW + t];
    else              su1[t - 128] = g_u[(b * HH + y1) * WW + (t - 128)];
    __syncthreads();
}

__device__ __forceinline__ float bilin(const float* su0, const float* su1,
                                       int j, float wy) {
    float xs = (float)j * (127.0f / 511.0f);
    int x0 = (int)xs;
    float wx = xs - (float)x0;
    int x1 = min(x0 + 1, WW - 1);
    float r0 = su0[x0] * (1.f - wy) + su1[x0] * wy;
    float r1 = su0[x1] * (1.f - wy) + su1[x1] * wy;
    return r0 * (1.f - wx) + r1 * wx;
}

__global__ void stats_kernel() {
    __shared__ float su0[128], su1[128];
    __shared__ float rs[8], rq[8];
    int row = blockIdx.x;
    int b = row >> 8, i = row & 255;
    float wy;
    stage_rows(su0, su1, b, i, wy);

    int t = threadIdx.x;
    float sum = 0.f, sq = 0.f;
#pragma unroll
    for (int rr = 0; rr < 2; rr++) {
        float v = bilin(su0, su1, t + rr * 256, wy);
        sum += v;
        sq  += v * v;
    }
#pragma unroll
    for (int o = 16; o; o >>= 1) {
        sum += __shfl_xor_sync(0xffffffffu, sum, o);
        sq  += __shfl_xor_sync(0xffffffffu, sq,  o);
    }
    if ((t & 31) == 0) { rs[t >> 5] = sum; rq[t >> 5] = sq; }
    __syncthreads();
    if (t == 0) {
        float a = 0.f, c = 0.f;
#pragma unroll
        for (int k = 0; k < 8; k++) { a += rs[k]; c += rq[k]; }
        g_psum[row] = a; g_psumsq[row] = c;
    }
}

__global__ void finalize_stats_kernel() {
    __shared__ float ss[NROWS], sq[NROWS];
    int t = threadIdx.x;
    ss[t] = g_psum[t]; sq[t] = g_psumsq[t];
    __syncthreads();
    for (int s = NROWS / 2; s; s >>= 1) {
        if (t < s) { ss[t] += ss[t + s]; sq[t] += sq[t + s]; }
        __syncthreads();
    }
    if (t == 0) {
        float inv_n = 1.0f / (float)NOUT;
        float mean  = ss[0] * inv_n;
        float var   = sq[0] * inv_n - mean * mean;
        g_stats[0] = mean;
        g_stats[1] = rsqrtf(var + 1e-5f);
    }
}

__global__ void output_kernel(float* __restrict__ out,
                              const float* __restrict__ gamma,
                              const float* __restrict__ beta) {
    __shared__ float su0[128], su1[128];
    int row = blockIdx.x;
    int b = row >> 8, i = row & 255;
    float wy;
    stage_rows(su0, su1, b, i, wy);

    float mean = g_stats[0], istd = g_stats[1];
    float gm = gamma[0], bt = beta[0];
    int t = threadIdx.x;
#pragma unroll
    for (int rr = 0; rr < 2; rr++) {
        int j = t + rr * 256;
        float v = bilin(su0, su1, j, wy);
        float y = (v - mean) * istd * gm + bt;
        out[row * WO + j] = 1.0f / (1.0f + expf(-y));
    }
}

// ===========================================================================
extern "C" void kernel_launch(void* const* d_in, const int* in_sizes, int n_in,
                              void* d_out, int out_size) {
    const float* p2    = (const float*)d_in[0];
    const float* convw = (const float*)d_in[1];
    const float* conv1 = (const float*)d_in[2];
    const float* gamma = (const float*)d_in[3];
    const float* beta  = (const float*)d_in[4];
    float* out = (float*)d_out;

    extract_M_kernel<<<256, 256>>>(convw);
    scnn_hmma_kernel<<<NCOL / NG, 256>>>(p2, conv1);
    stats_kernel<<<NROWS, 256>>>();
    finalize_stats_kernel<<<1, NROWS>>>();
    output_kernel<<<NROWS, 256>>>(out, gamma, beta);
}

// round 8
// speedup vs baseline: 1.6778x; 1.6778x over previous
#include <cuda_runtime.h>
#include <cuda_fp16.h>
#include <cstdint>

#define CC 256
#define WW 128
#define HH 64
#define BB 2
#define NCOL (BB*HH)
#define HO 256
#define WO 512
#define NOUT (BB*HO*WO)
#define NROWS 512             // output rows (b,i)

__device__ __half g_M[CC*CC];           // center-tap weights fp16, row-major [o][c]
__device__ float  g_u[NCOL*WW];
__device__ float  g_psum[NROWS];
__device__ float  g_psumsq[NROWS];

__device__ __forceinline__ uint32_t smem_u32(const void* p) {
    uint32_t a;
    asm("{ .reg .u64 t; cvta.to.shared.u64 t, %1; cvt.u32.u64 %0, t; }"
        : "=r"(a) : "l"(p));
    return a;
}

// ===========================================================================
__global__ void extract_M_kernel(const float* __restrict__ convw) {
    int i = blockIdx.x * 256 + threadIdx.x;
    g_M[i] = __float2half(convw[i * 9 + 4]);
}

// ===========================================================================
// HMMA double scan: 32 CTAs x 4 columns, 256 threads (R5 structure).
// Per step: D[256x8] = M[256x256] @ S[256x8], mma.sync m16n8k16.
// A = M resident in registers. B = S fp16 double-buffered smem, k-major
// 16B rows (k row = 8 halfs: 4 cols x {s1,s2}).
// u-reduction DEFERRED: partial carried across the barrier in a register,
// shfl-reduced in the shadow of the next step's LDSM/MMA stream; g_u drain
// lags two steps.
#define MMA_ASM(dd, a, b0r, b1r)                                              \
    asm volatile(                                                             \
        "mma.sync.aligned.m16n8k16.row.col.f32.f16.f16.f32 "                  \
        "{%0,%1,%2,%3}, {%4,%5,%6,%7}, {%8,%9}, {%0,%1,%2,%3};"               \
        : "+f"((dd)[0]), "+f"((dd)[1]), "+f"((dd)[2]), "+f"((dd)[3])          \
        : "r"((a)[0]), "r"((a)[1]), "r"((a)[2]), "r"((a)[3]),                 \
          "r"(b0r), "r"(b1r))

#define LDSM_T(L, addr)                                                       \
    asm volatile(                                                             \
        "ldmatrix.sync.aligned.m8n8.x4.trans.shared.b16 {%0,%1,%2,%3}, [%4];" \
        : "=r"((L)[0]), "=r"((L)[1]), "=r"((L)[2]), "=r"((L)[3])              \
        : "r"(addr))

__global__ void __launch_bounds__(256, 1) scnn_hmma_kernel(
        const float* __restrict__ p2, const float* __restrict__ w1g) {
    __shared__ __align__(128) __half Bbuf[2][CC * 8];   // 2 x 4KB
    __shared__ float wsum[2][8][4];

    const int tid  = threadIdx.x;
    const int wid  = tid >> 5;
    const int lane = tid & 31;
    const int tg   = lane & 3;
    const int g    = lane >> 2;
    const int col0 = blockIdx.x * 4;
    const int col  = col0 + tg;
    const int b    = col >> 6;
    const int h    = col & 63;

    // ---- A fragments: M rows [32*wid, 32*wid+32)
    uint32_t A[2][16][4];
#pragma unroll
    for (int tt = 0; tt < 2; tt++) {
        int rlo = 32 * wid + 16 * tt + g;
        const uint32_t* Mlo = reinterpret_cast<const uint32_t*>(g_M + rlo * CC);
        const uint32_t* Mhi = reinterpret_cast<const uint32_t*>(g_M + (rlo + 8) * CC);
#pragma unroll
        for (int kt = 0; kt < 16; kt++) {
            A[tt][kt][0] = Mlo[kt * 8 + tg];
            A[tt][kt][1] = Mhi[kt * 8 + tg];
            A[tt][kt][2] = Mlo[kt * 8 + tg + 4];
            A[tt][kt][3] = Mhi[kt * 8 + tg + 4];
        }
    }

    // this thread's 4 channel rows, w1 taps, x stream offsets
    int   ch[4];
    float w1v[4];
    int   off[4];
#pragma unroll
    for (int i = 0; i < 4; i++) {
        int tt = i >> 1, hh = i & 1;
        ch[i]  = 32 * wid + 16 * tt + 8 * hh + g;
        w1v[i] = w1g[ch[i]];
        off[i] = ((b * CC + ch[i]) * HH + h) * WW;
    }

    const uint32_t b32    = smem_u32(&Bbuf[0][0]);
    const uint32_t lmaddr = b32 + (uint32_t)lane * 16u;

    // ---- step 0: s1[0] = s2[0] = x[:,0]  (write buffer 0); u partial carried
    float xv[4];
    float u0 = 0.f;
#pragma unroll
    for (int i = 0; i < 4; i++) {
        float x0 = p2[off[i]];
        __half hx = __float2half_rn(x0);
        *(__half2*)&Bbuf[0][ch[i] * 8 + 2 * tg] = __halves2half2(hx, hx);
        u0 += w1v[i] * x0;
        xv[i] = p2[off[i] + 1];
    }

    for (int w = 1; w < WW; w++) {
        __syncthreads();

        const int rb = (w - 1) & 1;
        const int wb = rb ^ 1;
        const uint32_t base = lmaddr + (uint32_t)rb * (CC * 8 * 2);

        // issue all B-fragment loads first (async via scoreboard)
        uint32_t L[8][4];
#pragma unroll
        for (int m8 = 0; m8 < 8; m8++)
            LDSM_T(L[m8], base + (uint32_t)m8 * 512u);

        // deferred u-reduction of step w-1 (overlaps LDSM latency / MMA issue)
        {
            float t0 = u0;
            t0 += __shfl_xor_sync(0xffffffffu, t0, 4);
            t0 += __shfl_xor_sync(0xffffffffu, t0, 8);
            t0 += __shfl_xor_sync(0xffffffffu, t0, 16);
            if (lane < 4) wsum[(w - 1) & 1][wid][lane] = t0;
        }
        // drain step w-2 (written during iteration w-1, separated by the bar)
        if (w > 1 && tid < 4) {
            float s = 0.f;
#pragma unroll
            for (int q = 0; q < 8; q++) s += wsum[w & 1][q][tid];
            g_u[(col0 + tid) * WW + (129 - w)] = s;
        }

        // prefetch next x (independent of everything below)
        float xn[4] = {0.f, 0.f, 0.f, 0.f};
        if (w < WW - 1) {
#pragma unroll
            for (int i = 0; i < 4; i++) xn[i] = p2[off[i] + w + 1];
        }

        float d[2][4] = {{0.f,0.f,0.f,0.f},{0.f,0.f,0.f,0.f}};
        float e[2][4] = {{0.f,0.f,0.f,0.f},{0.f,0.f,0.f,0.f}};
#pragma unroll
        for (int m8 = 0; m8 < 8; m8++) {
#pragma unroll
            for (int tt = 0; tt < 2; tt++) {
                MMA_ASM(d[tt], A[tt][2 * m8],     L[m8][0], L[m8][1]);
                MMA_ASM(e[tt], A[tt][2 * m8 + 1], L[m8][2], L[m8][3]);
            }
        }

        u0 = 0.f;
#pragma unroll
        for (int i = 0; i < 4; i++) {
            const int tt = i >> 1, hh = i & 1;
            float r1  = fmaxf(d[tt][2*hh]   + e[tt][2*hh],   0.f);
            float r2  = fmaxf(d[tt][2*hh+1] + e[tt][2*hh+1], 0.f);
            float s1n = xv[i] + r1;
            float s2n = s1n + r2;
            u0 += w1v[i] * s2n;
            if (w < WW - 1) {
                *(__half2*)&Bbuf[wb][ch[i] * 8 + 2 * tg] =
                    __floats2half2_rn(s1n, s2n);
                xv[i] = xn[i];
            }
        }
    }

    // reduce step 127's u (slot 1), then drain steps 126 (slot 0) and 127
    {
        float t0 = u0;
        t0 += __shfl_xor_sync(0xffffffffu, t0, 4);
        t0 += __shfl_xor_sync(0xffffffffu, t0, 8);
        t0 += __shfl_xor_sync(0xffffffffu, t0, 16);
        if (lane < 4) wsum[1][wid][lane] = t0;
    }
    __syncthreads();
    if (tid < 4) {
        float s126 = 0.f, s127 = 0.f;
#pragma unroll
        for (int q = 0; q < 8; q++) {
            s126 += wsum[0][q][tid];
            s127 += wsum[1][q][tid];
        }
        g_u[(col0 + tid) * WW + 1] = s126;
        g_u[(col0 + tid) * WW + 0] = s127;
    }
}

// ===========================================================================
__device__ __forceinline__ void stage_rows(float* su0, float* su1,
                                           int b, int i, float& wy) {
    float ys = (float)i * (63.0f / 255.0f);
    int y0 = (int)ys;
    wy = ys - (float)y0;
    int y1 = min(y0 + 1, HH - 1);
    int t = threadIdx.x;
    if (t < 128)      su0[t]       = g_u[(b * HH + y0) * WW + t];
    else if (t < 256) su1[t - 128] = g_u[(b * HH + y1) * WW + (t - 128)];
}

__device__ __forceinline__ float bilin(const float* su0, const float* su1,
                                       int j, float wy) {
    float xs = (float)j * (127.0f / 511.0f);
    int x0 = (int)xs;
    float wx = xs - (float)x0;
    int x1 = min(x0 + 1, WW - 1);
    float r0 = su0[x0] * (1.f - wy) + su1[x0] * wy;
    float r1 = su0[x1] * (1.f - wy) + su1[x1] * wy;
    return r0 * (1.f - wx) + r1 * wx;
}

__global__ void stats_kernel() {
    __shared__ float su0[128], su1[128];
    __shared__ float rs[8], rq[8];
    int row = blockIdx.x;
    int b = row >> 8, i = row & 255;
    float wy;
    stage_rows(su0, su1, b, i, wy);
    __syncthreads();

    int t = threadIdx.x;
    float sum = 0.f, sq = 0.f;
#pragma unroll
    for (int rr = 0; rr < 2; rr++) {
        float v = bilin(su0, su1, t + rr * 256, wy);
        sum += v;
        sq  += v * v;
    }
#pragma unroll
    for (int o = 16; o; o >>= 1) {
        sum += __shfl_xor_sync(0xffffffffu, sum, o);
        sq  += __shfl_xor_sync(0xffffffffu, sq,  o);
    }
    if ((t & 31) == 0) { rs[t >> 5] = sum; rq[t >> 5] = sq; }
    __syncthreads();
    if (t == 0) {
        float a = 0.f, c = 0.f;
#pragma unroll
        for (int k = 0; k < 8; k++) { a += rs[k]; c += rq[k]; }
        g_psum[row] = a; g_psumsq[row] = c;
    }
}

// output kernel with finalize folded in: every block redundantly reduces the
// 512 partial sums (hot in L2), then applies BN + sigmoid to its row.
__global__ void output_kernel(float* __restrict__ out,
                              const float* __restrict__ gamma,
                              const float* __restrict__ beta) {
    __shared__ float su0[128], su1[128];
    __shared__ float rs[8], rq[8];
    __shared__ float stats2[2];
    int row = blockIdx.x;
    int b = row >> 8, i = row & 255;
    float wy;
    stage_rows(su0, su1, b, i, wy);

    int t = threadIdx.x;
    // reduce 512 partials: each thread takes 2
    float sum = g_psum[t] + g_psum[t + 256];
    float sq  = g_psumsq[t] + g_psumsq[t + 256];
#pragma unroll
    for (int o = 16; o; o >>= 1) {
        sum += __shfl_xor_sync(0xffffffffu, sum, o);
        sq  += __shfl_xor_sync(0xffffffffu, sq,  o);
    }
    if ((t & 31) == 0) { rs[t >> 5] = sum; rq[t >> 5] = sq; }
    __syncthreads();
    if (t == 0) {
        float a = 0.f, c = 0.f;
#pragma unroll
        for (int k = 0; k < 8; k++) { a += rs[k]; c += rq[k]; }
        float inv_n = 1.0f / (float)NOUT;
        float mean  = a * inv_n;
        float var   = c * inv_n - mean * mean;
        stats2[0] = mean;
        stats2[1] = rsqrtf(var + 1e-5f);
    }
    __syncthreads();

    float mean = stats2[0], istd = stats2[1];
    float gm = gamma[0], bt = beta[0];
#pragma unroll
    for (int rr = 0; rr < 2; rr++) {
        int j = t + rr * 256;
        float v = bilin(su0, su1, j, wy);
        float y = (v - mean) * istd * gm + bt;
        out[row * WO + j] = 1.0f / (1.0f + expf(-y));
    }
}

// ===========================================================================
extern "C" void kernel_launch(void* const* d_in, const int* in_sizes, int n_in,
                              void* d_out, int out_size) {
    const float* p2    = (const float*)d_in[0];
    const float* convw = (const float*)d_in[1];
    const float* conv1 = (const float*)d_in[2];
    const float* gamma = (const float*)d_in[3];
    const float* beta  = (const float*)d_in[4];
    float* out = (float*)d_out;

    extract_M_kernel<<<256, 256>>>(convw);
    scnn_hmma_kernel<<<32, 256>>>(p2, conv1);
    stats_kernel<<<NROWS, 256>>>();
    output_kernel<<<NROWS, 256>>>(out, gamma, beta);
}

// round 9
// speedup vs baseline: 2.7107x; 1.6156x over previous
#include <cuda_runtime.h>
#include <cuda_fp16.h>
#include <cstdint>

#define CC 256
#define WW 128
#define HH 64
#define BB 2
#define NCOL (BB*HH)
#define HO 256
#define WO 512
#define NOUT (BB*HO*WO)
#define NROWS 512             // output rows (b,i)

__device__ __half g_M[CC*CC];           // center-tap weights fp16, row-major [o][c]
__device__ float  g_u[NCOL*WW];
__device__ float  g_psum[NROWS];
__device__ float  g_psumsq[NROWS];

__device__ __forceinline__ uint32_t smem_u32(const void* p) {
    uint32_t a;
    asm("{ .reg .u64 t; cvta.to.shared.u64 t, %1; cvt.u32.u64 %0, t; }"
        : "=r"(a) : "l"(p));
    return a;
}

// ===========================================================================
// Kernel 0: extract center tap of conv_w -> packed fp16
__global__ void extract_M_kernel(const float* __restrict__ convw) {
    int i = blockIdx.x * 256 + threadIdx.x;
    g_M[i] = __float2half(convw[i * 9 + 4]);
}

// ===========================================================================
// Kernel A: HMMA-driven double scan (EXACT R5 structure — known-good timing).
// 32 CTAs x 4 columns, 256 threads. Per step: D[256x8] = M[256x256] @ S[256x8]
// via mma.sync m16n8k16; A = M resident in registers; B = S fp16 in
// double-buffered smem, k-major 16B rows; ldmatrix.x4.trans B loads.
#define MMA_ASM(dd, a, b0r, b1r)                                              \
    asm volatile(                                                             \
        "mma.sync.aligned.m16n8k16.row.col.f32.f16.f16.f32 "                  \
        "{%0,%1,%2,%3}, {%4,%5,%6,%7}, {%8,%9}, {%0,%1,%2,%3};"               \
        : "+f"((dd)[0]), "+f"((dd)[1]), "+f"((dd)[2]), "+f"((dd)[3])          \
        : "r"((a)[0]), "r"((a)[1]), "r"((a)[2]), "r"((a)[3]),                 \
          "r"(b0r), "r"(b1r))

__global__ void __launch_bounds__(256, 1) scnn_hmma_kernel(
        const float* __restrict__ p2, const float* __restrict__ w1g) {
    __shared__ __align__(128) __half Bbuf[2][CC * 8];   // [buf][k*8 + n] 8KB
    __shared__ float wsum[2][8][4];

    const int tid  = threadIdx.x;
    const int wid  = tid >> 5;
    const int lane = tid & 31;
    const int tg   = lane & 3;     // selects column of group (and n pair)
    const int g    = lane >> 2;
    const int col0 = blockIdx.x * 4;
    const int col  = col0 + tg;
    const int b    = col >> 6;
    const int h    = col & 63;

    // ---- A fragments: M rows [32*wid, 32*wid+32), resident in registers
    uint32_t A[2][16][4];
#pragma unroll
    for (int tt = 0; tt < 2; tt++) {
        int rlo = 32 * wid + 16 * tt + g;
        const uint32_t* Mlo = reinterpret_cast<const uint32_t*>(g_M + rlo * CC);
        const uint32_t* Mhi = reinterpret_cast<const uint32_t*>(g_M + (rlo + 8) * CC);
#pragma unroll
        for (int kt = 0; kt < 16; kt++) {
            A[tt][kt][0] = Mlo[kt * 8 + tg];
            A[tt][kt][1] = Mhi[kt * 8 + tg];
            A[tt][kt][2] = Mlo[kt * 8 + tg + 4];
            A[tt][kt][3] = Mhi[kt * 8 + tg + 4];
        }
    }

    // this thread's 4 channel rows and w1 taps
    int   ch[4];
    float w1v[4];
#pragma unroll
    for (int i = 0; i < 4; i++) {
        int tt = i >> 1, hh = i & 1;
        ch[i]  = 32 * wid + 16 * tt + 8 * hh + g;
        w1v[i] = w1g[ch[i]];
    }

    // x stream pointers: contiguous in w for fixed (b, ch, h)
    const float4* xp[4];
#pragma unroll
    for (int i = 0; i < 4; i++)
        xp[i] = reinterpret_cast<const float4*>(
            p2 + ((size_t)(b * CC + ch[i]) * HH + h) * WW);

    float4 cur[4], nxt[4];
#pragma unroll
    for (int i = 0; i < 4; i++) cur[i] = xp[i][0];

    const uint32_t b32    = smem_u32(&Bbuf[0][0]);
    const uint32_t lmaddr = b32 + (uint32_t)lane * 16u;

    // ---- step 0: s1[0] = s2[0] = x[:,0]  (write buffer 0)
    {
        float usum = 0.f;
#pragma unroll
        for (int i = 0; i < 4; i++) {
            float x0 = cur[i].x;
            __half hx = __float2half_rn(x0);
            *(__half2*)&Bbuf[0][ch[i] * 8 + 2 * tg] = __halves2half2(hx, hx);
            usum += w1v[i] * x0;
        }
        usum += __shfl_xor_sync(0xffffffffu, usum, 4);
        usum += __shfl_xor_sync(0xffffffffu, usum, 8);
        usum += __shfl_xor_sync(0xffffffffu, usum, 16);
        if (lane < 4) wsum[0][wid][lane] = usum;
    }

    for (int q = 0; q < 32; q++) {
#pragma unroll
        for (int j = 0; j < 4; j++) {
            const int w = 4 * q + 1 + j;
            if (w > 127) break;
            __syncthreads();
            // drain previous step's u reduction
            if (tid < 4) {
                float s = 0.f;
#pragma unroll
                for (int k8 = 0; k8 < 8; k8++) s += wsum[(w - 1) & 1][k8][tid];
                g_u[(col0 + tid) * WW + (WW - w)] = s;
            }

            const int rb = j & 1;           // read buffer = (w-1)&1
            const int wb = rb ^ 1;          // write buffer = w&1
            const uint32_t base = lmaddr + (uint32_t)rb * (CC * 8 * 2);

            uint32_t L[8][4];
#pragma unroll
            for (int m8 = 0; m8 < 8; m8++) {
                asm volatile(
                    "ldmatrix.sync.aligned.m8n8.x4.trans.shared.b16 "
                    "{%0,%1,%2,%3}, [%4];"
                    : "=r"(L[m8][0]), "=r"(L[m8][1]),
                      "=r"(L[m8][2]), "=r"(L[m8][3])
                    : "r"(base + (uint32_t)m8 * 512u));
            }

            // prefetch next x group while MMAs run
            if (j == 0 && q < 31) {
#pragma unroll
                for (int i = 0; i < 4; i++) nxt[i] = xp[i][q + 1];
            }

            float d[2][4] = {{0.f,0.f,0.f,0.f},{0.f,0.f,0.f,0.f}};
            float e[2][4] = {{0.f,0.f,0.f,0.f},{0.f,0.f,0.f,0.f}};
#pragma unroll
            for (int m8 = 0; m8 < 8; m8++) {
#pragma unroll
                for (int tt = 0; tt < 2; tt++) {
                    MMA_ASM(d[tt], A[tt][2 * m8],     L[m8][0], L[m8][1]);
                    MMA_ASM(e[tt], A[tt][2 * m8 + 1], L[m8][2], L[m8][3]);
                }
            }

            float usum = 0.f;
#pragma unroll
            for (int i = 0; i < 4; i++) {
                const int tt = i >> 1, hh = i & 1;
                float xvj = (j == 0) ? cur[i].y
                          : (j == 1) ? cur[i].z
                          : (j == 2) ? cur[i].w
                                     : nxt[i].x;
                float r1  = fmaxf(d[tt][2*hh]   + e[tt][2*hh],   0.f);
                float r2  = fmaxf(d[tt][2*hh+1] + e[tt][2*hh+1], 0.f);
                float s1n = xvj + r1;
                float s2n = s1n + r2;
                usum += w1v[i] * s2n;
                if (w < 127)
                    *(__half2*)&Bbuf[wb][ch[i] * 8 + 2 * tg] =
                        __halves2half2(__float2half_rn(s1n), __float2half_rn(s2n));
            }
            usum += __shfl_xor_sync(0xffffffffu, usum, 4);
            usum += __shfl_xor_sync(0xffffffffu, usum, 8);
            usum += __shfl_xor_sync(0xffffffffu, usum, 16);
            if (lane < 4) wsum[w & 1][wid][lane] = usum;

            if (j == 3) {
                cur[0] = nxt[0]; cur[1] = nxt[1];
                cur[2] = nxt[2]; cur[3] = nxt[3];
            }
        }
    }

    __syncthreads();
    if (tid < 4) {
        float s = 0.f;
#pragma unroll
        for (int k8 = 0; k8 < 8; k8++) s += wsum[1][k8][tid];   // w=127 -> buf 1
        g_u[(col0 + tid) * WW + 0] = s;
    }
}

// ===========================================================================
__device__ __forceinline__ void stage_rows(float* su0, float* su1,
                                           int b, int i, float& wy) {
    float ys = (float)i * (63.0f / 255.0f);
    int y0 = (int)ys;
    wy = ys - (float)y0;
    int y1 = min(y0 + 1, HH - 1);
    int t = threadIdx.x;
    if (t < 128)      su0[t]       = g_u[(b * HH + y0) * WW + t];
    else if (t < 256) su1[t - 128] = g_u[(b * HH + y1) * WW + (t - 128)];
}

__device__ __forceinline__ float bilin(const float* su0, const float* su1,
                                       int j, float wy) {
    float xs = (float)j * (127.0f / 511.0f);
    int x0 = (int)xs;
    float wx = xs - (float)x0;
    int x1 = min(x0 + 1, WW - 1);
    float r0 = su0[x0] * (1.f - wy) + su1[x0] * wy;
    float r1 = su0[x1] * (1.f - wy) + su1[x1] * wy;
    return r0 * (1.f - wx) + r1 * wx;
}

__global__ void stats_kernel() {
    __shared__ float su0[128], su1[128];
    __shared__ float rs[8], rq[8];
    int row = blockIdx.x;
    int b = row >> 8, i = row & 255;
    float wy;
    stage_rows(su0, su1, b, i, wy);
    __syncthreads();

    int t = threadIdx.x;
    float sum = 0.f, sq = 0.f;
#pragma unroll
    for (int rr = 0; rr < 2; rr++) {
        float v = bilin(su0, su1, t + rr * 256, wy);
        sum += v;
        sq  += v * v;
    }
#pragma unroll
    for (int o = 16; o; o >>= 1) {
        sum += __shfl_xor_sync(0xffffffffu, sum, o);
        sq  += __shfl_xor_sync(0xffffffffu, sq,  o);
    }
    if ((t & 31) == 0) { rs[t >> 5] = sum; rq[t >> 5] = sq; }
    __syncthreads();
    if (t == 0) {
        float a = 0.f, c = 0.f;
#pragma unroll
        for (int k = 0; k < 8; k++) { a += rs[k]; c += rq[k]; }
        g_psum[row] = a; g_psumsq[row] = c;
    }
}

// output kernel with finalize folded in: every block redundantly reduces the
// 512 partial sums (hot in L2), then applies BN + sigmoid to its row.
__global__ void output_kernel(float* __restrict__ out,
                              const float* __restrict__ gamma,
                              const float* __restrict__ beta) {
    __shared__ float su0[128], su1[128];
    __shared__ float rs[8], rq[8];
    __shared__ float stats2[2];
    int row = blockIdx.x;
    int b = row >> 8, i = row & 255;
    float wy;
    stage_rows(su0, su1, b, i, wy);

    int t = threadIdx.x;
    // reduce 512 partials: each thread takes 2
    float sum = g_psum[t] + g_psum[t + 256];
    float sq  = g_psumsq[t] + g_psumsq[t + 256];
#pragma unroll
    for (int o = 16; o; o >>= 1) {
        sum += __shfl_xor_sync(0xffffffffu, sum, o);
        sq  += __shfl_xor_sync(0xffffffffu, sq,  o);
    }
    if ((t & 31) == 0) { rs[t >> 5] = sum; rq[t >> 5] = sq; }
    __syncthreads();
    if (t == 0) {
        float a = 0.f, c = 0.f;
#pragma unroll
        for (int k = 0; k < 8; k++) { a += rs[k]; c += rq[k]; }
        float inv_n = 1.0f / (float)NOUT;
        float mean  = a * inv_n;
        float var   = c * inv_n - mean * mean;
        stats2[0] = mean;
        stats2[1] = rsqrtf(var + 1e-5f);
    }
    __syncthreads();

    float mean = stats2[0], istd = stats2[1];
    float gm = gamma[0], bt = beta[0];
#pragma unroll
    for (int rr = 0; rr < 2; rr++) {
        int j = t + rr * 256;
        float v = bilin(su0, su1, j, wy);
        float y = (v - mean) * istd * gm + bt;
        out[row * WO + j] = 1.0f / (1.0f + expf(-y));
    }
}

// ===========================================================================
extern "C" void kernel_launch(void* const* d_in, const int* in_sizes, int n_in,
                              void* d_out, int out_size) {
    const float* p2    = (const float*)d_in[0];
    const float* convw = (const float*)d_in[1];
    const float* conv1 = (const float*)d_in[2];
    const float* gamma = (const float*)d_in[3];
    const float* beta  = (const float*)d_in[4];
    float* out = (float*)d_out;

    extract_M_kernel<<<256, 256>>>(convw);
    scnn_hmma_kernel<<<32, 256>>>(p2, conv1);
    stats_kernel<<<NROWS, 256>>>();
    output_kernel<<<NROWS, 256>>>(out, gamma, beta);
}

// round 10
// speedup vs baseline: 2.9845x; 1.1010x over previous
#include <cuda_runtime.h>
#include <cuda_fp16.h>
#include <cstdint>

#define CC 256
#define WW 128
#define HH 64
#define BB 2
#define NCOL (BB*HH)
#define HO 256
#define WO 512
#define NOUT (BB*HO*WO)
#define NROWS 512             // output rows (b,i)

// per-fill transaction bytes: 1024 half2 B-state (4096B) + 32 u-partial floats (128B)
#define TXB 4224u

__device__ __half g_M[CC*CC];            // center-tap weights fp16, row-major [o][c]
__device__ float  g_upart[2][NCOL*WW];   // per-rank partial u
__device__ float  g_psum[NROWS];
__device__ float  g_psumsq[NROWS];

__device__ __forceinline__ uint32_t smem_u32(const void* p) {
    uint32_t a;
    asm("{ .reg .u64 t; cvta.to.shared.u64 t, %1; cvt.u32.u64 %0, t; }"
        : "=r"(a) : "l"(p));
    return a;
}
__device__ __forceinline__ uint32_t cluster_rank() {
    uint32_t r;
    asm("mov.u32 %0, %%cluster_ctarank;" : "=r"(r));
    return r;
}
__device__ __forceinline__ uint32_t mapa_u32(uint32_t addr, uint32_t rank) {
    uint32_t r;
    asm("mapa.shared::cluster.u32 %0, %1, %2;" : "=r"(r) : "r"(addr), "r"(rank));
    return r;
}
#define ST_ASYNC_U32(addr, val, mbar)                                         \
    asm volatile("st.async.shared::cluster.mbarrier::complete_tx::bytes.u32 " \
                 "[%0], %1, [%2];" :: "r"(addr), "r"(val), "r"(mbar) : "memory")
#define MBAR_INIT(mbar, cnt)                                                  \
    asm volatile("mbarrier.init.shared.b64 [%0], %1;"                         \
                 :: "r"(mbar), "r"((uint32_t)(cnt)) : "memory")
#define MBAR_EXPECT_TX(mbar, bytes)                                           \
    asm volatile("mbarrier.arrive.expect_tx.shared::cta.b64 _, [%0], %1;"     \
                 :: "r"(mbar), "r"((uint32_t)(bytes)) : "memory")
#define MBAR_WAIT(mbar, parity) do {                                          \
    uint32_t _m = (mbar), _p = (parity), _done;                               \
    asm volatile("{ .reg .pred p;\n\t"                                        \
        "mbarrier.try_wait.parity.acquire.cluster.shared::cta.b64 p, [%1], %2;\n\t" \
        "selp.b32 %0, 1, 0, p; }"                                             \
        : "=r"(_done) : "r"(_m), "r"(_p) : "memory");                         \
    if (!_done) {                                                             \
        asm volatile("{ .reg .pred P1;\n\t"                                   \
            "WL_%=:\n\t"                                                      \
            "mbarrier.try_wait.parity.acquire.cluster.shared::cta.b64 P1, [%0], %1, 0x989680;\n\t" \
            "@P1 bra.uni WD_%=;\n\t"                                          \
            "bra.uni WL_%=;\n\t"                                              \
            "WD_%=: }" :: "r"(_m), "r"(_p) : "memory");                       \
    }                                                                         \
} while (0)
#define CLUSTER_SYNC() do {                                                   \
    asm volatile("barrier.cluster.arrive.aligned;" ::: "memory");             \
    asm volatile("barrier.cluster.wait.aligned;"   ::: "memory");             \
} while (0)

// ===========================================================================
__global__ void extract_M_kernel(const float* __restrict__ convw) {
    int i = blockIdx.x * 256 + threadIdx.x;
    g_M[i] = __float2half(convw[i * 9 + 4]);
}

// ===========================================================================
// 2-CTA-cluster HMMA double scan. 64 CTAs = 32 clusters x 4 columns.
// Each CTA computes 128 output channels (rank*128..+128): 16 MMAs/warp/step.
// Per step each CTA writes its half of the new S into BOTH CTAs' B buffers
// via st.async (tx-counted); one mbarrier per buffer parity, count=1 arrival
// (tid0's expect_tx re-arm) + TXB bytes.
#define MMA_ASM(dd, a, b0r, b1r)                                              \
    asm volatile(                                                             \
        "mma.sync.aligned.m16n8k16.row.col.f32.f16.f16.f32 "                  \
        "{%0,%1,%2,%3}, {%4,%5,%6,%7}, {%8,%9}, {%0,%1,%2,%3};"               \
        : "+f"((dd)[0]), "+f"((dd)[1]), "+f"((dd)[2]), "+f"((dd)[3])          \
        : "r"((a)[0]), "r"((a)[1]), "r"((a)[2]), "r"((a)[3]),                 \
          "r"(b0r), "r"(b1r))

__global__ void __launch_bounds__(256, 1) __cluster_dims__(2, 1, 1)
scnn_hmma_kernel(const float* __restrict__ p2, const float* __restrict__ w1g) {
    __shared__ __align__(128) __half Bbuf[2][CC * 8];   // [buf][k*8 + n] 2x4KB
    __shared__ float wsum[2][8][4];
    __shared__ __align__(8) unsigned long long mbar[2];

    const int tid  = threadIdx.x;
    const int wid  = tid >> 5;
    const int lane = tid & 31;
    const int tg   = lane & 3;
    const int g    = lane >> 2;
    const int col0 = (blockIdx.x >> 1) * 4;
    const int col  = col0 + tg;
    const int b    = col >> 6;
    const int h    = col & 63;
    const uint32_t rank = cluster_rank();
    const uint32_t peer = rank ^ 1u;

    // ---- A fragments: this CTA's M rows [rank*128 + 16*wid, +16)
    uint32_t A[16][4];
    const int rlo = (int)rank * 128 + 16 * wid + g;
    {
        const uint32_t* Mlo = reinterpret_cast<const uint32_t*>(g_M + rlo * CC);
        const uint32_t* Mhi = reinterpret_cast<const uint32_t*>(g_M + (rlo + 8) * CC);
#pragma unroll
        for (int kt = 0; kt < 16; kt++) {
            A[kt][0] = Mlo[kt * 8 + tg];
            A[kt][1] = Mhi[kt * 8 + tg];
            A[kt][2] = Mlo[kt * 8 + tg + 4];
            A[kt][3] = Mhi[kt * 8 + tg + 4];
        }
    }

    // this thread's 2 channels (rows g, g+8 of its warp tile)
    const int ch0 = rlo;            // = rank*128 + 16*wid + g
    const int ch1 = rlo + 8;
    const float w1a = w1g[ch0];
    const float w1b = w1g[ch1];

    const float4* xpa = reinterpret_cast<const float4*>(
        p2 + ((size_t)(b * CC + ch0) * HH + h) * WW);
    const float4* xpb = reinterpret_cast<const float4*>(
        p2 + ((size_t)(b * CC + ch1) * HH + h) * WW);

    // smem addresses (local + peer)
    const uint32_t b32    = smem_u32(&Bbuf[0][0]);
    const uint32_t ws32   = smem_u32(&wsum[0][0][0]);
    const uint32_t bar32  = smem_u32(&mbar[0]);
    const uint32_t b32r   = mapa_u32(b32,  peer);
    const uint32_t bar32r = mapa_u32(bar32, peer);
    const uint32_t lmaddr = b32 + (uint32_t)lane * 16u;
    // per-thread B byte offsets for (ch, tg)
    const uint32_t bo0 = (uint32_t)(ch0 * 16 + tg * 4);
    const uint32_t bo1 = (uint32_t)(ch1 * 16 + tg * 4);

    if (tid == 0) { MBAR_INIT(bar32, 1); MBAR_INIT(bar32 + 8, 1); }
    __syncthreads();
    CLUSTER_SYNC();
    if (tid == 0) {
        MBAR_EXPECT_TX(bar32,     TXB);   // fill 0 of buffer 0 (step 0)
        MBAR_EXPECT_TX(bar32 + 8, TXB);   // fill 0 of buffer 1 (step 1)
    }

    // ---- step 0: s1[0] = s2[0] = x[:,0]  -> buffer 0 (both CTAs)
    float4 cura = xpa[0], curb = xpb[0];
    float4 nxta, nxtb;
    {
        float usum = w1a * cura.x + w1b * curb.x;
        usum += __shfl_xor_sync(0xffffffffu, usum, 4);
        usum += __shfl_xor_sync(0xffffffffu, usum, 8);
        usum += __shfl_xor_sync(0xffffffffu, usum, 16);

        __half2 v0h = __halves2half2(__float2half_rn(cura.x), __float2half_rn(cura.x));
        __half2 v1h = __halves2half2(__float2half_rn(curb.x), __float2half_rn(curb.x));
        uint32_t v0 = *reinterpret_cast<uint32_t*>(&v0h);
        uint32_t v1 = *reinterpret_cast<uint32_t*>(&v1h);
        ST_ASYNC_U32(b32  + bo0, v0, bar32);
        ST_ASYNC_U32(b32  + bo1, v1, bar32);
        ST_ASYNC_U32(b32r + bo0, v0, bar32r);
        ST_ASYNC_U32(b32r + bo1, v1, bar32r);
        if (lane < 4)
            ST_ASYNC_U32(ws32 + (uint32_t)((wid * 4 + lane) * 4),
                         __float_as_uint(usum), bar32);
    }

    for (int w = 1; w < WW; w++) {
        const int rb = (w - 1) & 1;
        const int wb = rb ^ 1;
        const uint32_t barL = bar32 + (uint32_t)rb * 8u;
        MBAR_WAIT(barL, (uint32_t)(((w - 1) >> 1) & 1));
        if (tid == 0 && w <= 125) MBAR_EXPECT_TX(barL, TXB);   // re-arm for fill at w+1

        // drain step w-1's u partial
        if (tid < 4) {
            float s = 0.f;
#pragma unroll
            for (int q8 = 0; q8 < 8; q8++) s += wsum[rb][q8][tid];
            g_upart[rank][(col0 + tid) * WW + (WW - w)] = s;
        }

        const uint32_t base = lmaddr + (uint32_t)rb * (CC * 8 * 2);
        uint32_t L[8][4];
#pragma unroll
        for (int m8 = 0; m8 < 8; m8++) {
            asm volatile(
                "ldmatrix.sync.aligned.m8n8.x4.trans.shared.b16 "
                "{%0,%1,%2,%3}, [%4];"
                : "=r"(L[m8][0]), "=r"(L[m8][1]), "=r"(L[m8][2]), "=r"(L[m8][3])
                : "r"(base + (uint32_t)m8 * 512u));
        }

        const int j = (w - 1) & 3;
        if (j == 0 && w + 4 <= WW) {       // prefetch next float4 group
            nxta = xpa[(w + 3) >> 2];
            nxtb = xpb[(w + 3) >> 2];
        }

        float d[4] = {0.f, 0.f, 0.f, 0.f};
        float e[4] = {0.f, 0.f, 0.f, 0.f};
#pragma unroll
        for (int m8 = 0; m8 < 8; m8++) {
            MMA_ASM(d, A[2 * m8],     L[m8][0], L[m8][1]);
            MMA_ASM(e, A[2 * m8 + 1], L[m8][2], L[m8][3]);
        }

        float xa = (j == 0) ? cura.y : (j == 1) ? cura.z : (j == 2) ? cura.w : nxta.x;
        float xb = (j == 0) ? curb.y : (j == 1) ? curb.z : (j == 2) ? curb.w : nxtb.x;

        float s1a = xa + fmaxf(d[0] + e[0], 0.f);
        float s2a = s1a + fmaxf(d[1] + e[1], 0.f);
        float s1b = xb + fmaxf(d[2] + e[2], 0.f);
        float s2b = s1b + fmaxf(d[3] + e[3], 0.f);

        float usum = w1a * s2a + w1b * s2b;
        usum += __shfl_xor_sync(0xffffffffu, usum, 4);
        usum += __shfl_xor_sync(0xffffffffu, usum, 8);
        usum += __shfl_xor_sync(0xffffffffu, usum, 16);

        if (w < WW - 1) {
            const uint32_t barWb  = bar32  + (uint32_t)wb * 8u;
            const uint32_t barWbR = bar32r + (uint32_t)wb * 8u;
            const uint32_t bufOff = (uint32_t)wb * (CC * 8 * 2);
            __half2 v0h = __floats2half2_rn(s1a, s2a);
            __half2 v1h = __floats2half2_rn(s1b, s2b);
            uint32_t v0 = *reinterpret_cast<uint32_t*>(&v0h);
            uint32_t v1 = *reinterpret_cast<uint32_t*>(&v1h);
            ST_ASYNC_U32(b32  + bufOff + bo0, v0, barWb);
            ST_ASYNC_U32(b32  + bufOff + bo1, v1, barWb);
            ST_ASYNC_U32(b32r + bufOff + bo0, v0, barWbR);
            ST_ASYNC_U32(b32r + bufOff + bo1, v1, barWbR);
            if (lane < 4)
                ST_ASYNC_U32(ws32 + (uint32_t)(((wb * 8 + wid) * 4 + lane) * 4),
                             __float_as_uint(usum), barWb);
        } else {
            if (lane < 4) wsum[1][wid][lane] = usum;   // step 127: plain STS
        }

        if (j == 3) { cura = nxta; curb = nxtb; }
    }

    __syncthreads();
    if (tid < 4) {
        float s = 0.f;
#pragma unroll
        for (int q8 = 0; q8 < 8; q8++) s += wsum[1][q8][tid];
        g_upart[rank][(col0 + tid) * WW + 0] = s;
    }
    CLUSTER_SYNC();
}

// ===========================================================================
__device__ __forceinline__ void stage_rows(float* su0, float* su1,
                                           int b, int i, float& wy) {
    float ys = (float)i * (63.0f / 255.0f);
    int y0 = (int)ys;
    wy = ys - (float)y0;
    int y1 = min(y0 + 1, HH - 1);
    int t = threadIdx.x;
    if (t < 128)
        su0[t] = g_upart[0][(b * HH + y0) * WW + t]
               + g_upart[1][(b * HH + y0) * WW + t];
    else if (t < 256)
        su1[t - 128] = g_upart[0][(b * HH + y1) * WW + (t - 128)]
                     + g_upart[1][(b * HH + y1) * WW + (t - 128)];
}

__device__ __forceinline__ float bilin(const float* su0, const float* su1,
                                       int j, float wy) {
    float xs = (float)j * (127.0f / 511.0f);
    int x0 = (int)xs;
    float wx = xs - (float)x0;
    int x1 = min(x0 + 1, WW - 1);
    float r0 = su0[x0] * (1.f - wy) + su1[x0] * wy;
    float r1 = su0[x1] * (1.f - wy) + su1[x1] * wy;
    return r0 * (1.f - wx) + r1 * wx;
}

__global__ void stats_kernel() {
    __shared__ float su0[128], su1[128];
    __shared__ float rs[8], rq[8];
    int row = blockIdx.x;
    int b = row >> 8, i = row & 255;
    float wy;
    stage_rows(su0, su1, b, i, wy);
    __syncthreads();

    int t = threadIdx.x;
    float sum = 0.f, sq = 0.f;
#pragma unroll
    for (int rr = 0; rr < 2; rr++) {
        float v = bilin(su0, su1, t + rr * 256, wy);
        sum += v;
        sq  += v * v;
    }
#pragma unroll
    for (int o = 16; o; o >>= 1) {
        sum += __shfl_xor_sync(0xffffffffu, sum, o);
        sq  += __shfl_xor_sync(0xffffffffu, sq,  o);
    }
    if ((t & 31) == 0) { rs[t >> 5] = sum; rq[t >> 5] = sq; }
    __syncthreads();
    if (t == 0) {
        float a = 0.f, c = 0.f;
#pragma unroll
        for (int k = 0; k < 8; k++) { a += rs[k]; c += rq[k]; }
        g_psum[row] = a; g_psumsq[row] = c;
    }
}

__global__ void output_kernel(float* __restrict__ out,
                              const float* __restrict__ gamma,
                              const float* __restrict__ beta) {
    __shared__ float su0[128], su1[128];
    __shared__ float rs[8], rq[8];
    __shared__ float stats2[2];
    int row = blockIdx.x;
    int b = row >> 8, i = row & 255;
    float wy;
    stage_rows(su0, su1, b, i, wy);

    int t = threadIdx.x;
    float sum = g_psum[t] + g_psum[t + 256];
    float sq  = g_psumsq[t] + g_psumsq[t + 256];
#pragma unroll
    for (int o = 16; o; o >>= 1) {
        sum += __shfl_xor_sync(0xffffffffu, sum, o);
        sq  += __shfl_xor_sync(0xffffffffu, sq,  o);
    }
    if ((t & 31) == 0) { rs[t >> 5] = sum; rq[t >> 5] = sq; }
    __syncthreads();
    if (t == 0) {
        float a = 0.f, c = 0.f;
#pragma unroll
        for (int k = 0; k < 8; k++) { a += rs[k]; c += rq[k]; }
        float inv_n = 1.0f / (float)NOUT;
        float mean  = a * inv_n;
        float var   = c * inv_n - mean * mean;
        stats2[0] = mean;
        stats2[1] = rsqrtf(var + 1e-5f);
    }
    __syncthreads();

    float mean = stats2[0], istd = stats2[1];
    float gm = gamma[0], bt = beta[0];
#pragma unroll
    for (int rr = 0; rr < 2; rr++) {
        int j = t + rr * 256;
        float v = bilin(su0, su1, j, wy);
        float y = (v - mean) * istd * gm + bt;
        out[row * WO + j] = 1.0f / (1.0f + expf(-y));
    }
}

// ===========================================================================
extern "C" void kernel_launch(void* const* d_in, const int* in_sizes, int n_in,
                              void* d_out, int out_size) {
    const float* p2    = (const float*)d_in[0];
    const float* convw = (const float*)d_in[1];
    const float* conv1 = (const float*)d_in[2];
    const float* gamma = (const float*)d_in[3];
    const float* beta  = (const float*)d_in[4];
    float* out = (float*)d_out;

    extract_M_kernel<<<256, 256>>>(convw);
    scnn_hmma_kernel<<<64, 256>>>(p2, conv1);
    stats_kernel<<<NROWS, 256>>>();
    output_kernel<<<NROWS, 256>>>(out, gamma, beta);
}